// round 1
// baseline (speedup 1.0000x reference)
#include <cuda_runtime.h>
#include <cuda_bf16.h>

// Quantum circuit: 4 qubits, AngleEmbedding(RY) + 6 StronglyEntanglingLayers,
// <Z_w> readout. One thread per batch sample; 16 complex amplitudes in registers.
//
// Stage 1 (init kernel, 1 block): compute the 24 Rot(phi,theta,omega) 2x2
//   complex matrices from quantum_weights into a __device__ global.
// Stage 2 (main kernel): per-sample state evolution fully unrolled.
//   CNOTs are compile-time register permutations (zero cost).

#define N_QUBITS 4
#define N_LAYERS 6
#define N_AMPS   16

// [layer*4 + wire][entry]: entry 0=m00, 1=m01, 2=m10, 3=m11
__device__ float2 g_rot[N_LAYERS * N_QUBITS][4];

__global__ void init_rot_kernel(const float* __restrict__ w) {
    int idx = threadIdx.x;           // 0..23 (one Rot matrix per thread)
    if (idx >= N_LAYERS * N_QUBITS) return;
    float phi   = w[idx * 3 + 0];
    float theta = w[idx * 3 + 1];
    float omega = w[idx * 3 + 2];
    float st, ct;  __sincosf(theta * 0.5f, &st, &ct);
    float sp, cp;  __sincosf((phi + omega) * 0.5f, &sp, &cp);
    float sm, cm;  __sincosf((phi - omega) * 0.5f, &sm, &cm);
    // m00 = e^{-i(phi+omega)/2} * c
    g_rot[idx][0] = make_float2( cp * ct, -sp * ct);
    // m01 = -e^{+i(phi-omega)/2} * s
    g_rot[idx][1] = make_float2(-cm * st, -sm * st);
    // m10 = e^{-i(phi-omega)/2} * s
    g_rot[idx][2] = make_float2( cm * st, -sm * st);
    // m11 = e^{+i(phi+omega)/2} * c
    g_rot[idx][3] = make_float2( cp * ct,  sp * ct);
}

__device__ __forceinline__ void apply_gate(float2* s, int wire,
                                           float2 u00, float2 u01,
                                           float2 u10, float2 u11) {
    const int stride = 8 >> wire;    // wire 0 is MSB of the amplitude index
    #pragma unroll
    for (int i = 0; i < N_AMPS; i++) {
        if (i & stride) continue;    // pick indices with this wire's bit = 0
        float2 a0 = s[i];
        float2 a1 = s[i + stride];
        float2 n0, n1;
        n0.x = u00.x * a0.x - u00.y * a0.y + u01.x * a1.x - u01.y * a1.y;
        n0.y = u00.x * a0.y + u00.y * a0.x + u01.x * a1.y + u01.y * a1.x;
        n1.x = u10.x * a0.x - u10.y * a0.y + u11.x * a1.x - u11.y * a1.y;
        n1.y = u10.x * a0.y + u10.y * a0.x + u11.x * a1.y + u11.y * a1.x;
        s[i]          = n0;
        s[i + stride] = n1;
    }
}

__global__ void __launch_bounds__(256)
quantum_circuit_kernel(const float* __restrict__ inputs,
                       float* __restrict__ out, int B) {
    int b = blockIdx.x * blockDim.x + threadIdx.x;
    if (b >= B) return;

    // ---- AngleEmbedding: product state, all-real amplitudes ----
    float4 x = __ldg(reinterpret_cast<const float4*>(inputs) + b);
    float c[N_QUBITS], sn[N_QUBITS];
    __sincosf(x.x * 0.5f, &sn[0], &c[0]);
    __sincosf(x.y * 0.5f, &sn[1], &c[1]);
    __sincosf(x.z * 0.5f, &sn[2], &c[2]);
    __sincosf(x.w * 0.5f, &sn[3], &c[3]);

    float2 s[N_AMPS];
    #pragma unroll
    for (int i = 0; i < N_AMPS; i++) {
        float v = ((i & 8) ? sn[0] : c[0])
                * ((i & 4) ? sn[1] : c[1])
                * ((i & 2) ? sn[2] : c[2])
                * ((i & 1) ? sn[3] : c[3]);
        s[i] = make_float2(v, 0.0f);
    }

    // ---- 6 StronglyEntanglingLayers ----
    #pragma unroll
    for (int l = 0; l < N_LAYERS; l++) {
        #pragma unroll
        for (int w = 0; w < N_QUBITS; w++) {
            const float2* m = g_rot[l * N_QUBITS + w];
            apply_gate(s, w, m[0], m[1], m[2], m[3]);
        }
        const int r = l % (N_QUBITS - 1) + 1;
        // ring of CNOTs: control w -> target (w+r)%4, sequential.
        #pragma unroll
        for (int w = 0; w < N_QUBITS; w++) {
            const int ctrl = w, tgt = (w + r) % N_QUBITS;
            const int cbit = 8 >> ctrl, tbit = 8 >> tgt;
            // swap amplitudes with ctrl=1, tgt=0  <->  ctrl=1, tgt=1
            #pragma unroll
            for (int i = 0; i < N_AMPS; i++) {
                if ((i & cbit) && !(i & tbit)) {
                    float2 tmp = s[i];
                    s[i] = s[i + tbit];
                    s[i + tbit] = tmp;
                }
            }
        }
    }

    // ---- <Z_w> readout ----
    float z0 = 0.f, z1 = 0.f, z2 = 0.f, z3 = 0.f;
    #pragma unroll
    for (int i = 0; i < N_AMPS; i++) {
        float p = s[i].x * s[i].x + s[i].y * s[i].y;
        z0 += (i & 8) ? -p : p;
        z1 += (i & 4) ? -p : p;
        z2 += (i & 2) ? -p : p;
        z3 += (i & 1) ? -p : p;
    }
    float4 zout = make_float4(z0, z1, z2, z3);
    reinterpret_cast<float4*>(out)[b] = zout;
}

extern "C" void kernel_launch(void* const* d_in, const int* in_sizes, int n_in,
                              void* d_out, int out_size) {
    const float* inputs  = (const float*)d_in[0];   // (B, 4) float32
    const float* weights = (const float*)d_in[1];   // (6, 4, 3) float32
    float* out = (float*)d_out;                     // (B, 4) float32
    int B = in_sizes[0] / N_QUBITS;

    init_rot_kernel<<<1, 32>>>(weights);
    int threads = 256;
    int blocks  = (B + threads - 1) / threads;
    quantum_circuit_kernel<<<blocks, threads>>>(inputs, out, B);
}

// round 3
// speedup vs baseline: 1.7100x; 1.7100x over previous
#include <cuda_runtime.h>
#include <cuda_bf16.h>

// 4-qubit circuit, algebraically collapsed:
//   state_after_embedding v  = real product state (kron of per-wire (cos,sin))
//   entangling block         = fixed 16x16 complex unitary U (weights only)
//   z_w                      = sign-tree over |U v|^2
//
// Stage 1 (init, 16 threads): evolve each basis column through the 24 Rot
//   gates + CNOT rings -> U, stored column-major in a __device__ global.
// Stage 2 (main): per-thread 2 samples; y = U v with packed fma.rn.f32x2
//   (re,im lanes together), U broadcast from shared memory.
//
// U storage: 16x16 complex = 256 float2 = 128 float4. Column i occupies
// float4 slots [i*8, i*8+8); slot j holds (U[2j][i], U[2j+1][i]).

#define N_QUBITS 4
#define N_LAYERS 6
#define N_AMPS   16
#define THREADS  128
#define NB       2          // samples per thread
#define U_F4     128        // float4 slots for the full U matrix

__device__ float4 g_U[U_F4];

__device__ __forceinline__ void apply_gate(float2* s, int wire,
                                           float2 u00, float2 u01,
                                           float2 u10, float2 u11) {
    const int stride = 8 >> wire;    // wire 0 is MSB of the amplitude index
    #pragma unroll
    for (int i = 0; i < N_AMPS; i++) {
        if (i & stride) continue;
        float2 a0 = s[i];
        float2 a1 = s[i + stride];
        float2 n0, n1;
        n0.x = u00.x * a0.x - u00.y * a0.y + u01.x * a1.x - u01.y * a1.y;
        n0.y = u00.x * a0.y + u00.y * a0.x + u01.x * a1.y + u01.y * a1.x;
        n1.x = u10.x * a0.x - u10.y * a0.y + u11.x * a1.x - u11.y * a1.y;
        n1.y = u10.x * a0.y + u10.y * a0.x + u11.x * a1.y + u11.y * a1.x;
        s[i]          = n0;
        s[i + stride] = n1;
    }
}

__global__ void init_u_kernel(const float* __restrict__ w) {
    int i = threadIdx.x;             // basis column index
    if (i >= N_AMPS) return;
    float2 s[N_AMPS];
    #pragma unroll
    for (int j = 0; j < N_AMPS; j++)
        s[j] = make_float2(j == i ? 1.0f : 0.0f, 0.0f);

    #pragma unroll
    for (int l = 0; l < N_LAYERS; l++) {
        #pragma unroll
        for (int q = 0; q < N_QUBITS; q++) {
            int idx = l * N_QUBITS + q;
            float phi   = w[idx * 3 + 0];
            float theta = w[idx * 3 + 1];
            float omega = w[idx * 3 + 2];
            float st, ct, sp, cp, sm, cm;
            __sincosf(theta * 0.5f, &st, &ct);
            __sincosf((phi + omega) * 0.5f, &sp, &cp);
            __sincosf((phi - omega) * 0.5f, &sm, &cm);
            float2 u00 = make_float2( cp * ct, -sp * ct);
            float2 u01 = make_float2(-cm * st, -sm * st);
            float2 u10 = make_float2( cm * st, -sm * st);
            float2 u11 = make_float2( cp * ct,  sp * ct);
            apply_gate(s, q, u00, u01, u10, u11);
        }
        const int r = l % (N_QUBITS - 1) + 1;
        #pragma unroll
        for (int q = 0; q < N_QUBITS; q++) {
            const int cbit = 8 >> q, tbit = 8 >> ((q + r) % N_QUBITS);
            #pragma unroll
            for (int a = 0; a < N_AMPS; a++) {
                if ((a & cbit) && !(a & tbit)) {
                    float2 t = s[a]; s[a] = s[a + tbit]; s[a + tbit] = t;
                }
            }
        }
    }
    float2* U = reinterpret_cast<float2*>(g_U);
    #pragma unroll
    for (int m = 0; m < N_AMPS; m++)
        U[i * N_AMPS + m] = s[m];    // column i contiguous: float2 slots [i*16, i*16+16)
}

// build v[16] = kron of per-wire (cos, sin) halves
__device__ __forceinline__ void embed(const float4 x, float* v) {
    float c0, s0, c1, s1, c2, s2, c3, s3;
    __sincosf(x.x * 0.5f, &s0, &c0);
    __sincosf(x.y * 0.5f, &s1, &c1);
    __sincosf(x.z * 0.5f, &s2, &c2);
    __sincosf(x.w * 0.5f, &s3, &c3);
    float p0 = c0 * c1, p1 = c0 * s1, p2 = s0 * c1, p3 = s0 * s1;
    float q0 = c2 * c3, q1 = c2 * s3, q2 = s2 * c3, q3 = s2 * s3;
    v[ 0] = p0 * q0;  v[ 1] = p0 * q1;  v[ 2] = p0 * q2;  v[ 3] = p0 * q3;
    v[ 4] = p1 * q0;  v[ 5] = p1 * q1;  v[ 6] = p1 * q2;  v[ 7] = p1 * q3;
    v[ 8] = p2 * q0;  v[ 9] = p2 * q1;  v[10] = p2 * q2;  v[11] = p2 * q3;
    v[12] = p3 * q0;  v[13] = p3 * q1;  v[14] = p3 * q2;  v[15] = p3 * q3;
}

__device__ __forceinline__ unsigned long long pack2(float lo, float hi) {
    unsigned long long r;
    asm("mov.b64 %0, {%1, %2};" : "=l"(r) : "f"(lo), "f"(hi));
    return r;
}

// readout: z_w = sum_m (1 - 2*bit_{3-w}(m)) * p[m], shared-subexpression tree
__device__ __forceinline__ float4 readout(const unsigned long long* y) {
    float p[N_AMPS];
    #pragma unroll
    for (int m = 0; m < N_AMPS; m++) {
        float re, im;
        asm("mov.b64 {%0, %1}, %2;" : "=f"(re), "=f"(im) : "l"(y[m]));
        p[m] = re * re + im * im;
    }
    float a0 = p[0]  + p[1],  a1 = p[2]  + p[3],  a2 = p[4]  + p[5],  a3 = p[6]  + p[7];
    float a4 = p[8]  + p[9],  a5 = p[10] + p[11], a6 = p[12] + p[13], a7 = p[14] + p[15];
    float z3 = ((p[0] - p[1]) + (p[2] - p[3])) + ((p[4] - p[5]) + (p[6] - p[7]))
             + ((p[8] - p[9]) + (p[10] - p[11])) + ((p[12] - p[13]) + (p[14] - p[15]));
    float b0 = a0 + a1, b1 = a2 + a3, b2 = a4 + a5, b3 = a6 + a7;
    float z2 = ((a0 - a1) + (a2 - a3)) + ((a4 - a5) + (a6 - a7));
    float z1 = (b0 - b1) + (b2 - b3);
    float z0 = (b0 + b1) - (b2 + b3);
    return make_float4(z0, z1, z2, z3);
}

__global__ void __launch_bounds__(THREADS)
quantum_main_kernel(const float* __restrict__ inputs,
                    float* __restrict__ out, int B) {
    __shared__ float4 sU[U_F4];
    if (threadIdx.x < U_F4) sU[threadIdx.x] = g_U[threadIdx.x];
    __syncthreads();

    const int b0 = blockIdx.x * (THREADS * NB) + threadIdx.x;
    const int b1 = b0 + THREADS;
    const float4* in4 = reinterpret_cast<const float4*>(inputs);

    float v0[N_AMPS], v1[N_AMPS];
    if (b0 < B) embed(__ldg(in4 + b0), v0);
    if (b1 < B) embed(__ldg(in4 + b1), v1);

    unsigned long long y0[N_AMPS], y1[N_AMPS];
    #pragma unroll
    for (int m = 0; m < N_AMPS; m++) { y0[m] = 0ull; y1[m] = 0ull; }

    // y = U v with packed (re,im) FFMA2; column i of U broadcast from smem
    #pragma unroll
    for (int i = 0; i < N_AMPS; i++) {
        unsigned long long vp0 = pack2(v0[i], v0[i]);
        unsigned long long vp1 = pack2(v1[i], v1[i]);
        #pragma unroll
        for (int j = 0; j < 8; j++) {
            float4 u2 = sU[i * 8 + j];              // (U[2j][i], U[2j+1][i])
            unsigned long long ua = pack2(u2.x, u2.y);
            unsigned long long ub = pack2(u2.z, u2.w);
            asm("fma.rn.f32x2 %0, %1, %2, %0;" : "+l"(y0[2*j    ]) : "l"(ua), "l"(vp0));
            asm("fma.rn.f32x2 %0, %1, %2, %0;" : "+l"(y0[2*j + 1]) : "l"(ub), "l"(vp0));
            asm("fma.rn.f32x2 %0, %1, %2, %0;" : "+l"(y1[2*j    ]) : "l"(ua), "l"(vp1));
            asm("fma.rn.f32x2 %0, %1, %2, %0;" : "+l"(y1[2*j + 1]) : "l"(ub), "l"(vp1));
        }
    }

    float4* out4 = reinterpret_cast<float4*>(out);
    if (b0 < B) out4[b0] = readout(y0);
    if (b1 < B) out4[b1] = readout(y1);
}

extern "C" void kernel_launch(void* const* d_in, const int* in_sizes, int n_in,
                              void* d_out, int out_size) {
    const float* inputs  = (const float*)d_in[0];   // (B, 4) float32
    const float* weights = (const float*)d_in[1];   // (6, 4, 3) float32
    float* out = (float*)d_out;                     // (B, 4) float32
    int B = in_sizes[0] / N_QUBITS;

    init_u_kernel<<<1, 32>>>(weights);
    int blocks = (B + THREADS * NB - 1) / (THREADS * NB);
    quantum_main_kernel<<<blocks, THREADS>>>(inputs, out, B);
}